// round 2
// baseline (speedup 1.0000x reference)
#include <cuda_runtime.h>
#include <math.h>

#define Bz 64
#define Lz 500
#define Dz 300
#define Fz 100
#define IDz 32

// ---------------- scratch (device globals; no allocation) ----------------
__device__ __align__(16) float g_WT[2 * 3 * Dz * Fz];     // dc weights transposed [side][k][d][f]
__device__ __align__(16) float g_FEAT[2 * Bz * Lz * Fz];  // conv features [side][b][l][f]
__device__ float g_SQ[2 * Bz * Lz];                       // sum_f feat^2
__device__ float g_ATT[2 * Bz * Lz];                      // [0]=user rowsum, [1]=item colsum
__device__ float g_COLP[8 * Bz * Lz];                     // per-ltile colsum partials (deterministic)
__device__ float g_S[2 * Bz * 3 * Fz];                    // pooled weighted sums

// ---------------- KT: transpose doc-cnn weights to [k][d][f] ----------------
__global__ void kt_kernel(const float* __restrict__ wu, const float* __restrict__ wi) {
    int idx = blockIdx.x * 256 + threadIdx.x;
    const int tot = 2 * 3 * Dz * Fz;
    if (idx >= tot) return;
    int side = idx / (3 * Dz * Fz);
    int r = idx % (3 * Dz * Fz);
    int k = r / (Dz * Fz);
    int r2 = r % (Dz * Fz);
    int d = r2 / Fz;
    int f = r2 % Fz;
    const float* w = side ? wi : wu;
    g_WT[idx] = w[(f * 3 + k) * Dz + d];
}

// ---------------- K3: fused gather + gate + doc conv + sq ----------------
// block = (ltile, b, side); 128 threads; L_TILE = 32
__global__ __launch_bounds__(128) void k3_kernel(
    const int* __restrict__ udoc, const int* __restrict__ idoc,
    const float* __restrict__ uemb, const float* __restrict__ iemb,
    const float* __restrict__ wc, const float* __restrict__ wcb,
    const float* __restrict__ udcb, const float* __restrict__ idcb)
{
    int lt = blockIdx.x, b = blockIdx.y, side = blockIdx.z;
    int l0 = lt * 32;
    const int* doc = (side ? idoc : udoc) + b * Lz;
    const float* emb = side ? iemb : uemb;
    const float* dcb = side ? idcb : udcb;

    __shared__ __align__(16) float e_sm[36][Dz];  // rows l0-2 .. l0+33
    __shared__ float t_sm[36][3];
    __shared__ float gate_sm[36];

    int tid = threadIdx.x;
    int warp = tid >> 5, lane = tid & 31;

    // gather 36 embedding rows (float4), zero outside [0,L)
    for (int i = tid; i < 36 * 75; i += 128) {
        int r = i / 75, c = i % 75;
        int l = l0 - 2 + r;
        float4 v = make_float4(0.f, 0.f, 0.f, 0.f);
        if (l >= 0 && l < Lz) {
            const float4* src = (const float4*)(emb + (long)doc[l] * Dz);
            v = src[c];
        }
        ((float4*)e_sm[r])[c] = v;
    }
    __syncthreads();

    // t_k[r] = sum_d e[r][d] * wc[k][d]
    for (int r = warp; r < 36; r += 4) {
        float a0 = 0.f, a1 = 0.f, a2 = 0.f;
        for (int d = lane; d < Dz; d += 32) {
            float ev = e_sm[r][d];
            a0 += ev * wc[d];
            a1 += ev * wc[Dz + d];
            a2 += ev * wc[2 * Dz + d];
        }
        for (int o = 16; o; o >>= 1) {
            a0 += __shfl_xor_sync(0xffffffffu, a0, o);
            a1 += __shfl_xor_sync(0xffffffffu, a1, o);
            a2 += __shfl_xor_sync(0xffffffffu, a2, o);
        }
        if (lane == 0) { t_sm[r][0] = a0; t_sm[r][1] = a1; t_sm[r][2] = a2; }
    }
    __syncthreads();

    // gate[l] = sigmoid(t0[l-1] + t1[l] + t2[l+1] + b)  (rows rr = 1..34 needed)
    if (tid >= 1 && tid <= 34) {
        float g = t_sm[tid - 1][0] + t_sm[tid][1] + t_sm[tid + 1][2] + wcb[0];
        gate_sm[tid] = 1.f / (1.f + expf(-g));
    }
    __syncthreads();

    // scale rows 1..34 in place
    for (int i = tid; i < 34 * 75; i += 128) {
        int r = 1 + i / 75, c = i % 75;
        float g = gate_sm[r];
        float4* p = (float4*)e_sm[r] + c;
        float4 v = *p;
        v.x *= g; v.y *= g; v.z *= g; v.w *= g;
        *p = v;
    }
    __syncthreads();

    // conv: warp handles 8 l's; lane handles f = 4*lane..4*lane+3 (lanes 0..24)
    int fl = lane < 25 ? lane : 24;
    const float4* w0p = (const float4*)(g_WT + ((side * 3 + 0) * Dz) * Fz) + fl;
    const float4* w1p = (const float4*)(g_WT + ((side * 3 + 1) * Dz) * Fz) + fl;
    const float4* w2p = (const float4*)(g_WT + ((side * 3 + 2) * Dz) * Fz) + fl;
    float acc[8][4];
#pragma unroll
    for (int i = 0; i < 8; i++)
#pragma unroll
        for (int j = 0; j < 4; j++) acc[i][j] = 0.f;

    int wl0 = warp * 8;  // l_local base for this warp
#pragma unroll 2
    for (int d = 0; d < Dz; d++) {
        float4 w0 = w0p[d * 25], w1 = w1p[d * 25], w2 = w2p[d * 25];
        float ev[10];
#pragma unroll
        for (int r = 0; r < 10; r++) ev[r] = e_sm[wl0 + 1 + r][d];
#pragma unroll
        for (int i = 0; i < 8; i++) {
            acc[i][0] += ev[i] * w0.x;     acc[i][1] += ev[i] * w0.y;
            acc[i][2] += ev[i] * w0.z;     acc[i][3] += ev[i] * w0.w;
            acc[i][0] += ev[i + 1] * w1.x; acc[i][1] += ev[i + 1] * w1.y;
            acc[i][2] += ev[i + 1] * w1.z; acc[i][3] += ev[i + 1] * w1.w;
            acc[i][0] += ev[i + 2] * w2.x; acc[i][1] += ev[i + 2] * w2.y;
            acc[i][2] += ev[i + 2] * w2.z; acc[i][3] += ev[i + 2] * w2.w;
        }
    }

    float bb0 = dcb[4 * fl + 0], bb1 = dcb[4 * fl + 1];
    float bb2 = dcb[4 * fl + 2], bb3 = dcb[4 * fl + 3];
    long base = (long)(side * Bz + b) * Lz;
#pragma unroll
    for (int i = 0; i < 8; i++) {
        int l = l0 + wl0 + i;
        float x0 = acc[i][0] + bb0, x1 = acc[i][1] + bb1;
        float x2 = acc[i][2] + bb2, x3 = acc[i][3] + bb3;
        float p = (lane < 25) ? (x0 * x0 + x1 * x1 + x2 * x2 + x3 * x3) : 0.f;
        for (int o = 16; o; o >>= 1) p += __shfl_xor_sync(0xffffffffu, p, o);
        if (l < Lz) {
            if (lane < 25) {
                float4 o4 = make_float4(x0, x1, x2, x3);
                ((float4*)(g_FEAT + (base + l) * Fz))[lane] = o4;
            }
            if (lane == 0) g_SQ[base + l] = p;
        }
    }
}

// ---------------- K4: pairwise attention row/col sums ----------------
// block = (ltile, b); 256 threads (16x16), 4x4 micro-tile, 64x64 gram tiles
__global__ __launch_bounds__(256) void k4_kernel() {
    extern __shared__ float sm[];
    float* u_sm = sm;                 // 64*101 (padded vs 16-way conflicts)
    float* v_sm = sm + 64 * 101;      // 64*100
    float* usq = v_sm + 64 * Fz;      // 64
    float* vsq = usq + 64;            // 64
    float* red = vsq + 64;            // 16*64
    int lt = blockIdx.x, b = blockIdx.y;
    int l0 = lt * 64;
    int tid = threadIdx.x, tx = tid & 15, ty = tid >> 4;
    const float* U = g_FEAT + (long)b * Lz * Fz;
    const float* V = g_FEAT + (long)(Bz + b) * Lz * Fz;

    for (int i = tid; i < 64 * Fz; i += 256) {
        int r = i / Fz, c = i % Fz;
        int l = l0 + r;
        u_sm[r * 101 + c] = (l < Lz) ? U[l * Fz + c] : 0.f;
    }
    if (tid < 64) { int l = l0 + tid; usq[tid] = (l < Lz) ? g_SQ[b * Lz + l] : 0.f; }

    float rowAcc[4] = {0.f, 0.f, 0.f, 0.f};
    for (int mt = 0; mt < 8; mt++) {
        int m0 = mt * 64;
        __syncthreads();
        for (int i = tid; i < 64 * Fz; i += 256) {
            int r = i / Fz, c = i % Fz;
            int m = m0 + r;
            v_sm[r * Fz + c] = (m < Lz) ? V[m * Fz + c] : 0.f;
        }
        if (tid < 64) { int m = m0 + tid; vsq[tid] = (m < Lz) ? g_SQ[(Bz + b) * Lz + m] : 0.f; }
        __syncthreads();

        float acc[4][4];
#pragma unroll
        for (int i = 0; i < 4; i++)
#pragma unroll
            for (int j = 0; j < 4; j++) acc[i][j] = 0.f;

#pragma unroll 2
        for (int f = 0; f < Fz; f++) {
            float uv[4], vv[4];
#pragma unroll
            for (int i = 0; i < 4; i++) uv[i] = u_sm[(tx * 4 + i) * 101 + f];
#pragma unroll
            for (int j = 0; j < 4; j++) vv[j] = v_sm[(ty * 4 + j) * Fz + f];
#pragma unroll
            for (int i = 0; i < 4; i++)
#pragma unroll
                for (int j = 0; j < 4; j++) acc[i][j] += uv[i] * vv[j];
        }

        float colP[4] = {0.f, 0.f, 0.f, 0.f};
#pragma unroll
        for (int i = 0; i < 4; i++) {
            int l = l0 + tx * 4 + i;
#pragma unroll
            for (int j = 0; j < 4; j++) {
                int m = m0 + ty * 4 + j;
                float sq = usq[tx * 4 + i] + vsq[ty * 4 + j] - 2.f * acc[i][j];
                float e = sqrtf(fmaxf(sq, 1e-12f));
                float a = 1.f / (1.f + e);
                if (l >= Lz || m >= Lz) a = 0.f;
                rowAcc[i] += a;
                colP[j] += a;
            }
        }
        // reduce colP over tx (width-16 shuffle); lane tx==0 holds sum over 64 l's
#pragma unroll
        for (int j = 0; j < 4; j++)
            for (int o = 8; o; o >>= 1) colP[j] += __shfl_xor_sync(0xffffffffu, colP[j], o, 16);
        if (tx == 0) {
#pragma unroll
            for (int j = 0; j < 4; j++) {
                int m = m0 + ty * 4 + j;
                if (m < Lz) g_COLP[((long)lt * Bz + b) * Lz + m] = colP[j];
            }
        }
    }
    __syncthreads();
#pragma unroll
    for (int i = 0; i < 4; i++) red[ty * 64 + tx * 4 + i] = rowAcc[i];
    __syncthreads();
    if (tid < 64) {
        float s = 0.f;
#pragma unroll
        for (int t = 0; t < 16; t++) s += red[t * 64 + tid];
        int l = l0 + tid;
        if (l < Lz) g_ATT[b * Lz + l] = s;
    }
}

// ---------------- K4b: deterministic reduce of colsum partials ----------------
__global__ void k4b_kernel() {
    int i = blockIdx.x * 256 + threadIdx.x;
    if (i >= Bz * Lz) return;
    float s = 0.f;
#pragma unroll
    for (int t = 0; t < 8; t++) s += g_COLP[t * Bz * Lz + i];
    g_ATT[Bz * Lz + i] = s;
}

// ---------------- K5a: pooled weighted sums S_k[b][f] ----------------
// The abs-conv + mean collapses to 3 weighted L-reductions of feat*att.
__global__ __launch_bounds__(128) void k5a_kernel() {
    int b = blockIdx.x, side = blockIdx.y;
    int f = threadIdx.x;
    if (f >= Fz) return;
    const float* fp = g_FEAT + (long)(side * Bz + b) * Lz * Fz + f;
    const float* ap = g_ATT + (side * Bz + b) * Lz;
    float s0 = 0.f, s1 = 0.f, s2 = 0.f;
    for (int l = 0; l < Lz; l++) {
        float p = fp[l * Fz] * ap[l];
        int lo0 = max(0, l - 1), hi0 = min(497, l + 1);
        int lo1 = max(1, l - 1), hi1 = min(498, l + 1);
        int lo2 = max(2, l - 1), hi2 = min(499, l + 1);
        s0 += (float)max(0, hi0 - lo0 + 1) * p;
        s1 += (float)max(0, hi1 - lo1 + 1) * p;
        s2 += (float)max(0, hi2 - lo2 + 1) * p;
    }
    float* Sb = g_S + (side * Bz + b) * 3 * Fz;
    Sb[f] = s0; Sb[Fz + f] = s1; Sb[2 * Fz + f] = s2;
}

// ---------------- K5b: abs-conv micro-GEMM + FC + id-emb gather + output ----------------
__global__ __launch_bounds__(128) void k5b_kernel(
    const float* __restrict__ uacw, const float* __restrict__ uacb,
    const float* __restrict__ iacw, const float* __restrict__ iacb,
    const float* __restrict__ ufcw, const float* __restrict__ ufcb,
    const float* __restrict__ ifcw, const float* __restrict__ ifcb,
    const float* __restrict__ uide, const float* __restrict__ iide,
    const int* __restrict__ uids, const int* __restrict__ iids,
    float* __restrict__ out)
{
    int b = blockIdx.x, side = blockIdx.y;
    __shared__ float abar[Fz];
    int tid = threadIdx.x;
    const float* Sb = g_S + (side * Bz + b) * 3 * Fz;
    const float* acw = side ? iacw : uacw;
    const float* acb = side ? iacb : uacb;
    if (tid < Fz) {
        float acc = 0.f;
        for (int t = 0; t < 3 * Fz; t++) acc += Sb[t] * acw[tid * 3 * Fz + t];
        abar[tid] = acb[tid] + acc * (1.f / 498.f);
    }
    __syncthreads();
    int off = side ? (Bz * 2 * IDz) : 0;
    if (tid < IDz) {
        const float* fcw = side ? ifcw : ufcw;
        const float* fcb = side ? ifcb : ufcb;
        float acc = fcb[tid];
        for (int f2 = 0; f2 < Fz; f2++) acc += abar[f2] * fcw[tid * Fz + f2];
        out[off + b * 2 * IDz + tid] = fmaxf(acc, 0.f);
    } else if (tid < 2 * IDz) {
        int id = tid - IDz;
        const float* et = side ? uide : iide;   // item_fea pairs with uid_emb; use_fea with iid_emb
        const int* ids = side ? uids : iids;
        out[off + b * 2 * IDz + IDz + id] = et[ids[b] * IDz + id];
    }
}

// ---------------- launch ----------------
extern "C" void kernel_launch(void* const* d_in, const int* in_sizes, int n_in,
                              void* d_out, int out_size) {
    const int* uids = (const int*)d_in[0];
    const int* iids = (const int*)d_in[1];
    const int* udoc = (const int*)d_in[2];
    const int* idoc = (const int*)d_in[3];
    const float* uemb = (const float*)d_in[4];
    const float* iemb = (const float*)d_in[5];
    const float* wc   = (const float*)d_in[6];
    const float* wcb  = (const float*)d_in[7];
    const float* udcw = (const float*)d_in[8];
    const float* udcb = (const float*)d_in[9];
    const float* idcw = (const float*)d_in[10];
    const float* idcb = (const float*)d_in[11];
    const float* uacw = (const float*)d_in[12];
    const float* uacb = (const float*)d_in[13];
    const float* iacw = (const float*)d_in[14];
    const float* iacb = (const float*)d_in[15];
    const float* ufcw = (const float*)d_in[16];
    const float* ufcb = (const float*)d_in[17];
    const float* ifcw = (const float*)d_in[18];
    const float* ifcb = (const float*)d_in[19];
    const float* uide = (const float*)d_in[20];
    const float* iide = (const float*)d_in[21];
    float* out = (float*)d_out;

    kt_kernel<<<(2 * 3 * Dz * Fz + 255) / 256, 256>>>(udcw, idcw);

    dim3 g3(16, Bz, 2);
    k3_kernel<<<g3, 128>>>(udoc, idoc, uemb, iemb, wc, wcb, udcb, idcb);

    const int k4_smem = (64 * 101 + 64 * Fz + 64 + 64 + 16 * 64) * (int)sizeof(float);
    cudaFuncSetAttribute(k4_kernel, cudaFuncAttributeMaxDynamicSharedMemorySize, k4_smem);
    dim3 g4(8, Bz);
    k4_kernel<<<g4, 256, k4_smem>>>();

    k4b_kernel<<<(Bz * Lz + 255) / 256, 256>>>();

    dim3 g5(Bz, 2);
    k5a_kernel<<<g5, 128>>>();
    k5b_kernel<<<g5, 128>>>(uacw, uacb, iacw, iacb, ufcw, ufcb, ifcw, ifcb,
                            uide, iide, uids, iids, out);
}

// round 5
// speedup vs baseline: 1.0033x; 1.0033x over previous
#include <cuda_runtime.h>
#include <math.h>
#include <stdint.h>

#define Bz 64
#define Lz 500
#define Dz 300
#define Fz 100
#define IDz 32

// ---------------- scratch (device globals; no allocation) ----------------
__device__ __align__(16) float g_WT[2 * 3 * Dz * Fz];     // dc weights transposed [side][k][d][f]
__device__ __align__(16) float g_FEAT[2 * Bz * Lz * Fz];  // conv features [side][b][l][f]
__device__ float g_SQ[2 * Bz * Lz];                       // sum_f feat^2
__device__ float g_ATT[2 * Bz * Lz];                      // [0]=user rowsum, [1]=item colsum
__device__ float g_COLP[8 * Bz * Lz];                     // per-ltile colsum partials (deterministic)
__device__ float g_S[2 * Bz * 3 * Fz];                    // pooled weighted sums

// ---------------- KT: transpose doc-cnn weights to [k][d][f] ----------------
__global__ void kt_kernel(const float* __restrict__ wu, const float* __restrict__ wi) {
    int idx = blockIdx.x * 256 + threadIdx.x;
    const int tot = 2 * 3 * Dz * Fz;
    if (idx >= tot) return;
    int side = idx / (3 * Dz * Fz);
    int r = idx % (3 * Dz * Fz);
    int k = r / (Dz * Fz);
    int r2 = r % (Dz * Fz);
    int d = r2 / Fz;
    int f = r2 % Fz;
    const float* w = side ? wi : wu;
    g_WT[idx] = w[(f * 3 + k) * Dz + d];
}

// ---------------- K3: fused gather + gate + doc conv + sq ----------------
// block = (ltile, b, side); 128 threads; L_TILE = 32
__global__ __launch_bounds__(128) void k3_kernel(
    const int* __restrict__ udoc, const int* __restrict__ idoc,
    const float* __restrict__ uemb, const float* __restrict__ iemb,
    const float* __restrict__ wc, const float* __restrict__ wcb,
    const float* __restrict__ udcb, const float* __restrict__ idcb)
{
    int lt = blockIdx.x, b = blockIdx.y, side = blockIdx.z;
    int l0 = lt * 32;
    const int* doc = (side ? idoc : udoc) + b * Lz;
    const float* emb = side ? iemb : uemb;
    const float* dcb = side ? idcb : udcb;

    __shared__ __align__(16) float e_sm[36][Dz];  // rows l0-2 .. l0+33
    __shared__ float t_sm[36][3];
    __shared__ float gate_sm[36];

    int tid = threadIdx.x;
    int warp = tid >> 5, lane = tid & 31;

    // gather 36 embedding rows (float4), zero outside [0,L)
    for (int i = tid; i < 36 * 75; i += 128) {
        int r = i / 75, c = i % 75;
        int l = l0 - 2 + r;
        float4 v = make_float4(0.f, 0.f, 0.f, 0.f);
        if (l >= 0 && l < Lz) {
            const float4* src = (const float4*)(emb + (long)doc[l] * Dz);
            v = src[c];
        }
        ((float4*)e_sm[r])[c] = v;
    }
    __syncthreads();

    // t_k[r] = sum_d e[r][d] * wc[k][d]
    for (int r = warp; r < 36; r += 4) {
        float a0 = 0.f, a1 = 0.f, a2 = 0.f;
        for (int d = lane; d < Dz; d += 32) {
            float ev = e_sm[r][d];
            a0 += ev * wc[d];
            a1 += ev * wc[Dz + d];
            a2 += ev * wc[2 * Dz + d];
        }
        for (int o = 16; o; o >>= 1) {
            a0 += __shfl_xor_sync(0xffffffffu, a0, o);
            a1 += __shfl_xor_sync(0xffffffffu, a1, o);
            a2 += __shfl_xor_sync(0xffffffffu, a2, o);
        }
        if (lane == 0) { t_sm[r][0] = a0; t_sm[r][1] = a1; t_sm[r][2] = a2; }
    }
    __syncthreads();

    // gate[l] = sigmoid(t0[l-1] + t1[l] + t2[l+1] + b)  (rows rr = 1..34 needed)
    if (tid >= 1 && tid <= 34) {
        float g = t_sm[tid - 1][0] + t_sm[tid][1] + t_sm[tid + 1][2] + wcb[0];
        gate_sm[tid] = 1.f / (1.f + expf(-g));
    }
    __syncthreads();

    // scale rows 1..34 in place
    for (int i = tid; i < 34 * 75; i += 128) {
        int r = 1 + i / 75, c = i % 75;
        float g = gate_sm[r];
        float4* p = (float4*)e_sm[r] + c;
        float4 v = *p;
        v.x *= g; v.y *= g; v.z *= g; v.w *= g;
        *p = v;
    }
    __syncthreads();

    // conv: warp handles 8 l's; lane handles f = 4*lane..4*lane+3 (lanes 0..24)
    int fl = lane < 25 ? lane : 24;
    const float4* w0p = (const float4*)(g_WT + ((side * 3 + 0) * Dz) * Fz) + fl;
    const float4* w1p = (const float4*)(g_WT + ((side * 3 + 1) * Dz) * Fz) + fl;
    const float4* w2p = (const float4*)(g_WT + ((side * 3 + 2) * Dz) * Fz) + fl;
    float acc[8][4];
#pragma unroll
    for (int i = 0; i < 8; i++)
#pragma unroll
        for (int j = 0; j < 4; j++) acc[i][j] = 0.f;

    int wl0 = warp * 8;  // l_local base for this warp
#pragma unroll 2
    for (int d = 0; d < Dz; d++) {
        float4 w0 = w0p[d * 25], w1 = w1p[d * 25], w2 = w2p[d * 25];
        float ev[10];
#pragma unroll
        for (int r = 0; r < 10; r++) ev[r] = e_sm[wl0 + 1 + r][d];
#pragma unroll
        for (int i = 0; i < 8; i++) {
            acc[i][0] += ev[i] * w0.x;     acc[i][1] += ev[i] * w0.y;
            acc[i][2] += ev[i] * w0.z;     acc[i][3] += ev[i] * w0.w;
            acc[i][0] += ev[i + 1] * w1.x; acc[i][1] += ev[i + 1] * w1.y;
            acc[i][2] += ev[i + 1] * w1.z; acc[i][3] += ev[i + 1] * w1.w;
            acc[i][0] += ev[i + 2] * w2.x; acc[i][1] += ev[i + 2] * w2.y;
            acc[i][2] += ev[i + 2] * w2.z; acc[i][3] += ev[i + 2] * w2.w;
        }
    }

    float bb0 = dcb[4 * fl + 0], bb1 = dcb[4 * fl + 1];
    float bb2 = dcb[4 * fl + 2], bb3 = dcb[4 * fl + 3];
    long base = (long)(side * Bz + b) * Lz;
#pragma unroll
    for (int i = 0; i < 8; i++) {
        int l = l0 + wl0 + i;
        float x0 = acc[i][0] + bb0, x1 = acc[i][1] + bb1;
        float x2 = acc[i][2] + bb2, x3 = acc[i][3] + bb3;
        float p = (lane < 25) ? (x0 * x0 + x1 * x1 + x2 * x2 + x3 * x3) : 0.f;
        for (int o = 16; o; o >>= 1) p += __shfl_xor_sync(0xffffffffu, p, o);
        if (l < Lz) {
            if (lane < 25) {
                float4 o4 = make_float4(x0, x1, x2, x3);
                ((float4*)(g_FEAT + (base + l) * Fz))[lane] = o4;
            }
            if (lane == 0) g_SQ[base + l] = p;
        }
    }
}

// ---------------- K4: pairwise attention row/col sums (tensor cores, 3xTF32) --
// block = (ltile, b); 256 threads = 8 warps; M=64 (u rows) x N=64 (v rows),
// K=100 (padded to 104). Warp grid 2(m) x 4(n); each warp 32x16 via m16n8k8.
#define UST 108  // smem row stride: 108%32=12, 12*g+tg covers all banks -> conflict-free

__device__ __forceinline__ void tf32_split(float x, uint32_t& hi, uint32_t& lo) {
    uint32_t h;
    asm("cvt.rna.tf32.f32 %0, %1;" : "=r"(h) : "f"(x));
    float r = x - __uint_as_float(h);
    uint32_t l;
    asm("cvt.rna.tf32.f32 %0, %1;" : "=r"(l) : "f"(r));
    hi = h; lo = l;
}

__device__ __forceinline__ void mma_tf32(float* c, const uint32_t* a, const uint32_t* b) {
    asm("mma.sync.aligned.m16n8k8.row.col.f32.tf32.tf32.f32 "
        "{%0,%1,%2,%3},{%4,%5,%6,%7},{%8,%9},{%0,%1,%2,%3};"
        : "+f"(c[0]), "+f"(c[1]), "+f"(c[2]), "+f"(c[3])
        : "r"(a[0]), "r"(a[1]), "r"(a[2]), "r"(a[3]), "r"(b[0]), "r"(b[1]));
}

__global__ __launch_bounds__(256) void k4_kernel() {
    extern __shared__ float sm[];
    float* u_sm = sm;                    // 64*UST
    float* v_sm = u_sm + 64 * UST;       // 64*UST
    float* usq = v_sm + 64 * UST;        // 64
    float* vsq = usq + 64;               // 64
    float* red = vsq + 64;               // 8*32
    float* colsm = red + 8 * 32;         // 64

    int lt = blockIdx.x, b = blockIdx.y;
    int l0 = lt * 64;
    int tid = threadIdx.x;
    int w = tid >> 5, lane = tid & 31;
    int wm = w >> 2, wn = w & 3;          // warp m-half (0..1), n-quarter (0..3)
    int g = lane >> 2, tg = lane & 3;     // mma groupID / thread-in-group

    const float* U = g_FEAT + (long)b * Lz * Fz;
    const float* V = g_FEAT + (long)(Bz + b) * Lz * Fz;

    for (int i = tid; i < 64 * UST; i += 256) {
        int r = i / UST, c = i - r * UST;
        int l = l0 + r;
        u_sm[r * UST + c] = (l < Lz && c < Fz) ? U[l * Fz + c] : 0.f;
    }
    if (tid < 64) { int l = l0 + tid; usq[tid] = (l < Lz) ? g_SQ[b * Lz + l] : 0.f; }
    __syncthreads();

    // cache usq for this thread's 4 fixed rows
    float usq_r[2][2];
#pragma unroll
    for (int mt = 0; mt < 2; mt++)
#pragma unroll
        for (int h = 0; h < 2; h++)
            usq_r[mt][h] = usq[wm * 32 + mt * 16 + g + 8 * h];

    float rowAcc[2][2] = {{0.f, 0.f}, {0.f, 0.f}};
    float colAcc[8][2][2];
#pragma unroll
    for (int vt = 0; vt < 8; vt++)
#pragma unroll
        for (int nt = 0; nt < 2; nt++) { colAcc[vt][nt][0] = 0.f; colAcc[vt][nt][1] = 0.f; }

    for (int vt = 0; vt < 8; vt++) {
        int m0 = vt * 64;
        for (int i = tid; i < 64 * UST; i += 256) {
            int r = i / UST, c = i - r * UST;
            int m = m0 + r;
            v_sm[r * UST + c] = (m < Lz && c < Fz) ? V[m * Fz + c] : 0.f;
        }
        if (tid < 64) { int m = m0 + tid; vsq[tid] = (m < Lz) ? g_SQ[(Bz + b) * Lz + m] : 0.f; }
        __syncthreads();

        float acc[2][2][4];
#pragma unroll
        for (int mt = 0; mt < 2; mt++)
#pragma unroll
            for (int nt = 0; nt < 2; nt++)
#pragma unroll
                for (int ci = 0; ci < 4; ci++) acc[mt][nt][ci] = 0.f;

#pragma unroll
        for (int kt = 0; kt < 13; kt++) {
            int k0 = kt * 8;
            uint32_t ahi[2][4], alo[2][4];
#pragma unroll
            for (int mt = 0; mt < 2; mt++) {
                int r0 = wm * 32 + mt * 16;
                float a0 = u_sm[(r0 + g) * UST + k0 + tg];
                float a1 = u_sm[(r0 + g + 8) * UST + k0 + tg];
                float a2 = u_sm[(r0 + g) * UST + k0 + tg + 4];
                float a3 = u_sm[(r0 + g + 8) * UST + k0 + tg + 4];
                tf32_split(a0, ahi[mt][0], alo[mt][0]);
                tf32_split(a1, ahi[mt][1], alo[mt][1]);
                tf32_split(a2, ahi[mt][2], alo[mt][2]);
                tf32_split(a3, ahi[mt][3], alo[mt][3]);
            }
            uint32_t bhi[2][2], blo[2][2];
#pragma unroll
            for (int nt = 0; nt < 2; nt++) {
                int nc = wn * 16 + nt * 8 + g;
                float b0 = v_sm[nc * UST + k0 + tg];
                float b1 = v_sm[nc * UST + k0 + tg + 4];
                tf32_split(b0, bhi[nt][0], blo[nt][0]);
                tf32_split(b1, bhi[nt][1], blo[nt][1]);
            }
#pragma unroll
            for (int mt = 0; mt < 2; mt++)
#pragma unroll
                for (int nt = 0; nt < 2; nt++) {
                    mma_tf32(acc[mt][nt], ahi[mt], bhi[nt]);
                    mma_tf32(acc[mt][nt], alo[mt], bhi[nt]);
                    mma_tf32(acc[mt][nt], ahi[mt], blo[nt]);
                }
        }

        // epilogue: att = 1/(1+sqrt(max(usq+vsq-2*gram, eps)))
#pragma unroll
        for (int mt = 0; mt < 2; mt++)
#pragma unroll
            for (int nt = 0; nt < 2; nt++)
#pragma unroll
                for (int ci = 0; ci < 4; ci++) {
                    int h = ci >> 1, e = ci & 1;
                    int lrow = wm * 32 + mt * 16 + g + 8 * h;
                    int lcol = wn * 16 + nt * 8 + 2 * tg + e;
                    int l = l0 + lrow, m = m0 + lcol;
                    float sq = usq_r[mt][h] + vsq[lcol] - 2.f * acc[mt][nt][ci];
                    float a = 1.f / (1.f + sqrtf(fmaxf(sq, 1e-12f)));
                    if (l >= Lz || m >= Lz) a = 0.f;
                    rowAcc[mt][h] += a;
                    colAcc[vt][nt][e] += a;
                }
        __syncthreads();
    }

    // ---- row sums (user att): reduce over tg lanes, then over 4 n-warps ----
#pragma unroll
    for (int mt = 0; mt < 2; mt++)
#pragma unroll
        for (int h = 0; h < 2; h++) {
            float s = rowAcc[mt][h];
            s += __shfl_xor_sync(0xffffffffu, s, 1);
            s += __shfl_xor_sync(0xffffffffu, s, 2);
            rowAcc[mt][h] = s;
        }
    if (tg == 0) {
#pragma unroll
        for (int mt = 0; mt < 2; mt++)
#pragma unroll
            for (int h = 0; h < 2; h++)
                red[w * 32 + mt * 16 + 8 * h + g] = rowAcc[mt][h];
    }
    __syncthreads();
    if (tid < 64) {
        int half = tid >> 5, r = tid & 31;
        float s = 0.f;
#pragma unroll
        for (int q = 0; q < 4; q++) s += red[(half * 4 + q) * 32 + r];
        int l = l0 + half * 32 + r;
        if (l < Lz) g_ATT[b * Lz + l] = s;
    }

    // ---- col sums (item att partials): reduce over g, then over 2 m-warps ----
    for (int vt = 0; vt < 8; vt++) {
        float cs[2][2];
#pragma unroll
        for (int nt = 0; nt < 2; nt++)
#pragma unroll
            for (int e = 0; e < 2; e++) {
                float s = colAcc[vt][nt][e];
                s += __shfl_xor_sync(0xffffffffu, s, 4);
                s += __shfl_xor_sync(0xffffffffu, s, 8);
                s += __shfl_xor_sync(0xffffffffu, s, 16);
                cs[nt][e] = s;
            }
        __syncthreads();
        if (wm == 0 && g == 0) {
#pragma unroll
            for (int nt = 0; nt < 2; nt++)
#pragma unroll
                for (int e = 0; e < 2; e++)
                    colsm[wn * 16 + nt * 8 + 2 * tg + e] = cs[nt][e];
        }
        __syncthreads();
        if (wm == 1 && g == 0) {
#pragma unroll
            for (int nt = 0; nt < 2; nt++)
#pragma unroll
                for (int e = 0; e < 2; e++)
                    colsm[wn * 16 + nt * 8 + 2 * tg + e] += cs[nt][e];
        }
        __syncthreads();
        if (tid < 64) {
            int m = vt * 64 + tid;
            if (m < Lz) g_COLP[((long)lt * Bz + b) * Lz + m] = colsm[tid];
        }
    }
}

// ---------------- K4b: deterministic reduce of colsum partials ----------------
__global__ void k4b_kernel() {
    int i = blockIdx.x * 256 + threadIdx.x;
    if (i >= Bz * Lz) return;
    float s = 0.f;
#pragma unroll
    for (int t = 0; t < 8; t++) s += g_COLP[t * Bz * Lz + i];
    g_ATT[Bz * Lz + i] = s;
}

// ---------------- K5a: pooled weighted sums S_k[b][f] ----------------
__global__ __launch_bounds__(128) void k5a_kernel() {
    int b = blockIdx.x, side = blockIdx.y;
    int f = threadIdx.x;
    if (f >= Fz) return;
    const float* fp = g_FEAT + (long)(side * Bz + b) * Lz * Fz + f;
    const float* ap = g_ATT + (side * Bz + b) * Lz;
    float s0 = 0.f, s1 = 0.f, s2 = 0.f;
    for (int l = 0; l < Lz; l++) {
        float p = fp[l * Fz] * ap[l];
        int lo0 = max(0, l - 1), hi0 = min(497, l + 1);
        int lo1 = max(1, l - 1), hi1 = min(498, l + 1);
        int lo2 = max(2, l - 1), hi2 = min(499, l + 1);
        s0 += (float)max(0, hi0 - lo0 + 1) * p;
        s1 += (float)max(0, hi1 - lo1 + 1) * p;
        s2 += (float)max(0, hi2 - lo2 + 1) * p;
    }
    float* Sb = g_S + (side * Bz + b) * 3 * Fz;
    Sb[f] = s0; Sb[Fz + f] = s1; Sb[2 * Fz + f] = s2;
}

// ---------------- K5b: abs-conv micro-GEMM + FC + id-emb gather + output ----------------
__global__ __launch_bounds__(128) void k5b_kernel(
    const float* __restrict__ uacw, const float* __restrict__ uacb,
    const float* __restrict__ iacw, const float* __restrict__ iacb,
    const float* __restrict__ ufcw, const float* __restrict__ ufcb,
    const float* __restrict__ ifcw, const float* __restrict__ ifcb,
    const float* __restrict__ uide, const float* __restrict__ iide,
    const int* __restrict__ uids, const int* __restrict__ iids,
    float* __restrict__ out)
{
    int b = blockIdx.x, side = blockIdx.y;
    __shared__ float abar[Fz];
    int tid = threadIdx.x;
    const float* Sb = g_S + (side * Bz + b) * 3 * Fz;
    const float* acw = side ? iacw : uacw;
    const float* acb = side ? iacb : uacb;
    if (tid < Fz) {
        float acc = 0.f;
        for (int t = 0; t < 3 * Fz; t++) acc += Sb[t] * acw[tid * 3 * Fz + t];
        abar[tid] = acb[tid] + acc * (1.f / 498.f);
    }
    __syncthreads();
    int off = side ? (Bz * 2 * IDz) : 0;
    if (tid < IDz) {
        const float* fcw = side ? ifcw : ufcw;
        const float* fcb = side ? ifcb : ufcb;
        float acc = fcb[tid];
        for (int f2 = 0; f2 < Fz; f2++) acc += abar[f2] * fcw[tid * Fz + f2];
        out[off + b * 2 * IDz + tid] = fmaxf(acc, 0.f);
    } else if (tid < 2 * IDz) {
        int id = tid - IDz;
        const float* et = side ? uide : iide;   // item_fea pairs with uid_emb; use_fea with iid_emb
        const int* ids = side ? uids : iids;
        out[off + b * 2 * IDz + IDz + id] = et[ids[b] * IDz + id];
    }
}

// ---------------- launch ----------------
extern "C" void kernel_launch(void* const* d_in, const int* in_sizes, int n_in,
                              void* d_out, int out_size) {
    const int* uids = (const int*)d_in[0];
    const int* iids = (const int*)d_in[1];
    const int* udoc = (const int*)d_in[2];
    const int* idoc = (const int*)d_in[3];
    const float* uemb = (const float*)d_in[4];
    const float* iemb = (const float*)d_in[5];
    const float* wc   = (const float*)d_in[6];
    const float* wcb  = (const float*)d_in[7];
    const float* udcw = (const float*)d_in[8];
    const float* udcb = (const float*)d_in[9];
    const float* idcw = (const float*)d_in[10];
    const float* idcb = (const float*)d_in[11];
    const float* uacw = (const float*)d_in[12];
    const float* uacb = (const float*)d_in[13];
    const float* iacw = (const float*)d_in[14];
    const float* iacb = (const float*)d_in[15];
    const float* ufcw = (const float*)d_in[16];
    const float* ufcb = (const float*)d_in[17];
    const float* ifcw = (const float*)d_in[18];
    const float* ifcb = (const float*)d_in[19];
    const float* uide = (const float*)d_in[20];
    const float* iide = (const float*)d_in[21];
    float* out = (float*)d_out;

    kt_kernel<<<(2 * 3 * Dz * Fz + 255) / 256, 256>>>(udcw, idcw);

    dim3 g3(16, Bz, 2);
    k3_kernel<<<g3, 128>>>(udoc, idoc, uemb, iemb, wc, wcb, udcb, idcb);

    const int k4_smem = (2 * 64 * UST + 64 + 64 + 8 * 32 + 64) * (int)sizeof(float);
    cudaFuncSetAttribute(k4_kernel, cudaFuncAttributeMaxDynamicSharedMemorySize, k4_smem);
    dim3 g4(8, Bz);
    k4_kernel<<<g4, 256, k4_smem>>>();

    k4b_kernel<<<(Bz * Lz + 255) / 256, 256>>>();

    dim3 g5(Bz, 2);
    k5a_kernel<<<g5, 128>>>();
    k5b_kernel<<<g5, 128>>>(uacw, uacb, iacw, iacb, ufcw, ufcb, ifcw, ifcb,
                            uide, iide, uids, iids, out);
}